// round 10
// baseline (speedup 1.0000x reference)
#include <cuda_runtime.h>

// FMFMNeuronInhib: T=1024 LIF steps over B=16384 neurons. HBM stream.
// R10: R7 algorithm (4 balanced chunks of 400 steps, WARM=192, depth-2 U=8
// register prefetch, evict_last warm-up loads, streaming main loads/stores)
// with 2 neurons per thread: float4 input loads, float2 stores. R7-R9 showed
// achieved BW pinned at 5.5-5.6 TB/s across TPB 64/128/256 at minimal
// traffic (246MB) -> per-request transaction overhead is the suspect.
// Halve request count at LSU/L1tex/LTS by doubling access width.

#define T_STEPS 1024
#define BATCH   16384
#define NPAIRS  (BATCH / 2)                          // 8192 float4 lanes
#define NCHUNK  4
#define WARM    192
#define L_TAIL  208                                  // stored, chunks 1..3
#define L_HEAD  (T_STEPS - (NCHUNK - 1) * L_TAIL)    // 400, chunk 0
#define U       8
#define TPB     64
#define XSTR    ((size_t)NPAIRS)                     // float4 stride per step
#define OSTR    ((size_t)NPAIRS)                     // float2 stride per step

// evict_last access policy (fraction 1.0)
__device__ __forceinline__ unsigned long long make_keep_policy() {
    unsigned long long pol;
    asm("createpolicy.fractional.L2::evict_last.b64 %0, 1.0;" : "=l"(pol));
    return pol;
}

// First-of-two-readers load: keep in L2 until the trailing reader arrives.
__device__ __forceinline__ float4 ldg_keep4(const float4* p, unsigned long long pol) {
    float4 v;
    asm("ld.global.nc.L2::cache_hint.v4.f32 {%0,%1,%2,%3}, [%4], %5;"
        : "=f"(v.x), "=f"(v.y), "=f"(v.z), "=f"(v.w) : "l"(p), "l"(pol));
    return v;
}

template <bool STORE, bool PREFETCH, bool KEEP>
__device__ __forceinline__ void win(
    float4* __restrict__ buf,        // consumed; refilled from `pre` if PREFETCH
    const float4* __restrict__ pre,  // absolute src of window t+2U
    unsigned long long pol,
    float& mem0, float& inh0, float& mem1, float& inh1,
    float w0, float w1, float wi,
    float2* __restrict__ spk, float2* __restrict__ memo, int tbase)
{
#pragma unroll
    for (int u = 0; u < U; u++) {
        const float4 v = buf[u];   // {x0_n0, x1_n0, x0_n1, x1_n1}
        if (PREFETCH)
            buf[u] = KEEP ? ldg_keep4(pre + (size_t)u * XSTR, pol)
                          : __ldcs(pre + (size_t)u * XSTR);

        // neuron 0
        inh0 = fmaf(0.6f, inh0, v.x);
        float cur0 = fmaf(w0, v.x, w1 * v.y);
        cur0 = fmaf(wi, inh0, cur0);
        const float r0 = (mem0 > 1.0f) ? 1.0f : 0.0f;
        mem0 = fmaf(0.9f, mem0, cur0 - r0);
        // neuron 1
        inh1 = fmaf(0.6f, inh1, v.z);
        float cur1 = fmaf(w0, v.z, w1 * v.w);
        cur1 = fmaf(wi, inh1, cur1);
        const float r1 = (mem1 > 1.0f) ? 1.0f : 0.0f;
        mem1 = fmaf(0.9f, mem1, cur1 - r1);

        if (STORE) {
            float2 s, m;
            s.x = (mem0 > 1.0f) ? 1.0f : 0.0f;
            s.y = (mem1 > 1.0f) ? 1.0f : 0.0f;
            m.x = mem0; m.y = mem1;
            __stcs(spk  + (size_t)(tbase + u) * OSTR, s);
            __stcs(memo + (size_t)(tbase + u) * OSTR, m);
        }
    }
}

__global__ void __launch_bounds__(TPB, 1) fmfm_kernel(
    const float4* __restrict__ x,      // [T, B/2] quads (2 neurons x 2 ch)
    const float*  __restrict__ w_exc,  // [2] = {0.7, 1.0}
    const float*  __restrict__ w_inh,  // [1] = {-1.0}
    float*        __restrict__ out)    // [2, T, B]: spk_rec then mem_rec
{
    const int nb    = NPAIRS / TPB;                // blocks per chunk (128)
    const int chunk = blockIdx.x / nb;
    const int b     = (blockIdx.x % nb) * TPB + threadIdx.x;  // pair index

    const float w0 = __ldg(&w_exc[0]);
    const float w1 = __ldg(&w_exc[1]);
    const float wi = __ldg(&w_inh[0]);

    const unsigned long long pol = make_keep_policy();

    // Chunk 0: store [0, 400), no warm-up (400 steps total).
    // Chunk i>=1: store [400 + (i-1)*208, +208), warm-up 192 (400 steps total).
    const int cs = (chunk == 0) ? 0 : L_HEAD + (chunk - 1) * L_TAIL;
    const int ce = (chunk == 0) ? L_HEAD : cs + L_TAIL;
    const int t0 = (chunk == 0) ? 0 : cs - WARM;

    const float4* xb   = x + b;
    float2*       spk  = (float2*)out + b;
    float2*       memo = (float2*)(out + (size_t)T_STEPS * BATCH) + b;

    float mem0 = 0.0f, inh0 = 0.0f, mem1 = 0.0f, inh1 = 0.0f;

    // Prologue: prefetch windows t0 and t0+U.
    float4 buf0[U], buf1[U];
    if (chunk == 0) {
#pragma unroll
        for (int u = 0; u < U; u++)
            buf0[u] = __ldcs(xb + (size_t)(t0 + u) * XSTR);
#pragma unroll
        for (int u = 0; u < U; u++)
            buf1[u] = __ldcs(xb + (size_t)(t0 + U + u) * XSTR);
    } else {
#pragma unroll
        for (int u = 0; u < U; u++)
            buf0[u] = ldg_keep4(xb + (size_t)(t0 + u) * XSTR, pol);
#pragma unroll
        for (int u = 0; u < U; u++)
            buf1[u] = ldg_keep4(xb + (size_t)(t0 + U + u) * XSTR, pol);
    }

    int t = t0;
    // Warm-up: advance state, no stores, evict_last loads (first reader of
    // data the trailing chunk's main loop re-reads). Empty for chunk 0.
    for (; t < cs; t += 2 * U) {
        win<false, true, true>(buf0, xb + (size_t)(t + 2 * U) * XSTR, pol,
                               mem0, inh0, mem1, inh1, w0, w1, wi, spk, memo, t);
        win<false, true, true>(buf1, xb + (size_t)(t + 3 * U) * XSTR, pol,
                               mem0, inh0, mem1, inh1, w0, w1, wi, spk, memo, t + U);
    }
    // Main stored region: streaming loads (we are the last reader).
    for (; t < ce - 2 * U; t += 2 * U) {
        win<true, true, false>(buf0, xb + (size_t)(t + 2 * U) * XSTR, pol,
                               mem0, inh0, mem1, inh1, w0, w1, wi, spk, memo, t);
        win<true, true, false>(buf1, xb + (size_t)(t + 3 * U) * XSTR, pol,
                               mem0, inh0, mem1, inh1, w0, w1, wi, spk, memo, t + U);
    }
    // Epilogue: last two windows.
    win<true, false, false>(buf0, nullptr, pol,
                            mem0, inh0, mem1, inh1, w0, w1, wi, spk, memo, t);
    win<true, false, false>(buf1, nullptr, pol,
                            mem0, inh0, mem1, inh1, w0, w1, wi, spk, memo, t + U);
}

extern "C" void kernel_launch(void* const* d_in, const int* in_sizes, int n_in,
                              void* d_out, int out_size) {
    const float* x     = (const float*)d_in[0];  // spike_seq [1024,16384,2]
    const float* w_exc = (const float*)d_in[1];  // [1,2]
    const float* w_inh = (const float*)d_in[2];  // scalar
    float* out = (float*)d_out;                  // [2,1024,16384]

    fmfm_kernel<<<(NPAIRS / TPB) * NCHUNK, TPB>>>((const float4*)x, w_exc, w_inh, out);
}